// round 5
// baseline (speedup 1.0000x reference)
#include <cuda_runtime.h>
#include <cstdint>

#define BATCH 32768
#define NODES 1024
#define NC 24
#define THREADS 128
#define NBLK 12
#define GRID (148 * NBLK)        // 1776 blocks: one wave at 12 blocks/SM
#define DEPTH 3
#define L2E 1.4426950408889634f
#define LN2 0.6931471805599453f

__device__ float    g_partial[GRID];
__device__ unsigned g_count = 0;   // self-resetting ticket (graph-replay safe)

__device__ __forceinline__ void cp_async16(uint32_t dst, const float* src) {
    asm volatile("cp.async.cg.shared.global [%0], [%1], 16;\n" :: "r"(dst), "l"(src));
}
__device__ __forceinline__ float ex2(float x) {
    float r; asm("ex2.approx.ftz.f32 %0, %1;" : "=f"(r) : "f"(x)); return r;
}
__device__ __forceinline__ float lg2(float x) {
    float r; asm("lg2.approx.ftz.f32 %0, %1;" : "=f"(r) : "f"(x)); return r;
}

__global__ void __launch_bounds__(THREADS, NBLK) tree_loss(
    const float* __restrict__ fs, const int* __restrict__ labels,
    float* __restrict__ out)
{
    __shared__ float    sbuf[DEPTH][NODES];   // 12 KB ring
    __shared__ float    s_z[4], s_S[4];
    __shared__ float    s_red[THREADS];
    __shared__ unsigned s_ticket;

    const int tid  = threadIdx.x;
    const int warp = tid >> 5;
    const int lane = tid & 31;
    const int b    = blockIdx.x;
    const int foff = 8 * tid;                 // this thread's 8 floats in the row

    // ---- prologue: prefetch rows b, b+GRID into stages 0,1 ----
    {
        const float* src = fs + (size_t)b * NODES + foff;
        uint32_t d = (uint32_t)__cvta_generic_to_shared(&sbuf[0][foff]);
        cp_async16(d, src); cp_async16(d + 16, src + 4);
    }
    asm volatile("cp.async.commit_group;");
    {
        const float* src = fs + (size_t)(b + GRID) * NODES + foff;  // < BATCH always
        uint32_t d = (uint32_t)__cvta_generic_to_shared(&sbuf[1][foff]);
        cp_async16(d, src); cp_async16(d + 16, src + 4);
    }
    asm volatile("cp.async.commit_group;");

    const int pbase   = (tid % 3) * 8;        // (8*tid) % 24
    const bool hasPar = (tid >= 3);           // threads 0..2 cover nodes 0..23

    float acc = 0.f;
    int row = b;
    int cs = 0, ps = 2;                       // compute stage, prefetch stage

    while (row < BATCH) {
        // prefetch row + 2*GRID into stage ps
        const int pr = row + 2 * GRID;
        if (pr < BATCH) {
            const float* src = fs + (size_t)pr * NODES + foff;
            uint32_t d = (uint32_t)__cvta_generic_to_shared(&sbuf[ps][foff]);
            cp_async16(d, src); cp_async16(d + 16, src + 4);
        }
        asm volatile("cp.async.commit_group;");  // always: lockstep group count

        const int label = __ldg(labels + row);   // broadcast, issued early

        asm volatile("cp.async.wait_group 2;" ::: "memory");
        __syncthreads();                          // stage cs fully loaded

        const float* __restrict__ buf = sbuf[cs];

        // -- per-thread 8 elements --
        const float4* __restrict__ b4 = reinterpret_cast<const float4*>(buf);
        float4 va = b4[2 * tid], vb = b4[2 * tid + 1];
        float p0=0.f,p1=0.f,p2=0.f,p3=0.f,p4=0.f,p5=0.f,p6=0.f,p7=0.f;
        if (hasPar) {
            const float4* __restrict__ pb =
                reinterpret_cast<const float4*>(buf + pbase);  // 32B aligned
            float4 pa = pb[0], pc = pb[1];
            p0 = pa.x*L2E; p1 = pa.y*L2E; p2 = pa.z*L2E; p3 = pa.w*L2E;
            p4 = pc.x*L2E; p5 = pc.y*L2E; p6 = pc.z*L2E; p7 = pc.w*L2E;
        }
        float t0 = ex2(__fmaf_rn(va.x, L2E, p0));
        float t1 = ex2(__fmaf_rn(va.y, L2E, p1));
        float t2 = ex2(__fmaf_rn(va.z, L2E, p2));
        float t3 = ex2(__fmaf_rn(va.w, L2E, p3));
        float t4 = ex2(__fmaf_rn(vb.x, L2E, p4));
        float t5 = ex2(__fmaf_rn(vb.y, L2E, p5));
        float t6 = ex2(__fmaf_rn(vb.z, L2E, p6));
        float t7 = ex2(__fmaf_rn(vb.w, L2E, p7));
        float zp = ((t0 + t1) + (t2 + t3)) + ((t4 + t5) + (t6 + t7));
        #pragma unroll
        for (int off = 16; off; off >>= 1)
            zp += __shfl_xor_sync(0xffffffffu, zp, off);
        if (lane == 0) s_z[warp] = zp;

        // pre-barrier buf reads needed by the epilogue
        float mval = 0.f, pval = 0.f;
        if (tid == 0) { mval = buf[label]; pval = buf[label % NC]; }

        const bool coarse = (label < NC);         // block-uniform
        if (coarse) {                              // rare (~2.3%)
            const int mmax = (1023 - label) / 24;  // 41-ish
            float S = 0.f;
            const int m = tid + 1;
            if (m <= mmax) S = ex2(buf[label + 24 * m] * L2E);
            #pragma unroll
            for (int off = 16; off; off >>= 1)
                S += __shfl_xor_sync(0xffffffffu, S, off);
            if (lane == 0) s_S[warp] = S;
        }

        __syncthreads();                           // s_z/s_S ready; buf reads done

        if (tid == 0) {
            const float zsum = (s_z[0] + s_z[1]) + (s_z[2] + s_z[3]);
            float lgm;
            if (coarse) {
                const float S = (s_S[0] + s_S[1]) + (s_S[2] + s_S[3]);
                lgm = mval * L2E + lg2(1.f + S);   // log2(E_label*(1+S))
            } else {
                lgm = (mval + pval) * L2E;         // log2(exp(fs[l]+fs[l%24]))
            }
            acc += (lg2(1.f + zsum) - lgm) * LN2;
        }

        row += GRID;
        cs = (cs == DEPTH - 1) ? 0 : cs + 1;
        ps = (ps == DEPTH - 1) ? 0 : ps + 1;
    }

    // ---- per-block result + deterministic fused final reduction ----
    if (tid == 0) {
        g_partial[b] = acc;
        __threadfence();
        s_ticket = atomicAdd(&g_count, 1u);
    }
    __syncthreads();

    if (s_ticket == GRID - 1) {                    // last block, fixed-order sum
        float s = 0.f;
        #pragma unroll 2
        for (int k = tid; k < GRID; k += THREADS) s += g_partial[k];
        s_red[tid] = s;
        __syncthreads();
        #pragma unroll
        for (int off = THREADS / 2; off; off >>= 1) {
            if (tid < off) s_red[tid] += s_red[tid + off];
            __syncthreads();
        }
        if (tid == 0) {
            out[0] = s_red[0] * (1.0f / (float)BATCH);
            g_count = 0;                           // reset for next graph replay
        }
    }
}

extern "C" void kernel_launch(void* const* d_in, const int* in_sizes, int n_in,
                              void* d_out, int out_size)
{
    const float* fs     = (const float*)d_in[0];
    const int*   labels = (const int*)d_in[1];
    // d_in[2] = stateSpace: compile-time-known structure, unused.
    tree_loss<<<GRID, THREADS>>>(fs, labels, (float*)d_out);
}

// round 6
// speedup vs baseline: 1.0899x; 1.0899x over previous
#include <cuda_runtime.h>
#include <cstdint>

#define BATCH 32768
#define NODES 1024
#define NC 24
#define THREADS 128
#define GRID 740                 // 148 SMs * 5 blocks: exactly one wave
#define NW (GRID * 4)            // 2960 warps, ~11 rows each
#define L2E 1.4426950408889634f
#define LN2 0.6931471805599453f

__device__ float    g_partial[GRID];
__device__ unsigned g_count = 0;   // self-resetting ticket (graph-replay safe)

__device__ __forceinline__ float ex2(float x) {
    float r; asm("ex2.approx.ftz.f32 %0, %1;" : "=f"(r) : "f"(x)); return r;
}
__device__ __forceinline__ float lg2(float x) {
    float r; asm("lg2.approx.ftz.f32 %0, %1;" : "=f"(r) : "f"(x)); return r;
}

// Compute loss for one row given its 32 per-lane values in v[8] (float4).
// fr = row base pointer (row's lines are L1-resident from the v loads).
__device__ __forceinline__ float row_loss(
    const float4* __restrict__ v, const float* __restrict__ fr,
    int label, float mval, float pval, int lane)
{
    // parents: 3 broadcast single-line LDG.128, L1 hits (line 0 of this row)
    const int b0 = (4 * lane) % 24;
    int b1 = b0 + 8;  if (b1 >= 24) b1 -= 24;
    int b2 = b1 + 8;  if (b2 >= 24) b2 -= 24;
    const float4 q0 = __ldg(reinterpret_cast<const float4*>(fr + b0));
    const float4 q1 = __ldg(reinterpret_cast<const float4*>(fr + b1));
    const float4 q2 = __ldg(reinterpret_cast<const float4*>(fr + b2));
    const float p[3][4] = {
        { q0.x*L2E, q0.y*L2E, q0.z*L2E, q0.w*L2E },
        { q1.x*L2E, q1.y*L2E, q1.z*L2E, q1.w*L2E },
        { q2.x*L2E, q2.y*L2E, q2.z*L2E, q2.w*L2E } };

    float z0 = 0.f, z1 = 0.f, z2 = 0.f, z3 = 0.f;
    #pragma unroll
    for (int i = 0; i < 8; ++i) {
        const int pi = i % 3;              // compile-time after unroll
        const float4 a = v[i];
        float t0, t1, t2, t3;
        if (i == 0) {                      // nodes 4*lane+j < 24 for lanes 0..5
            const bool noPar = (lane < 6);
            t0 = ex2(__fmaf_rn(a.x, L2E, noPar ? 0.f : p[0][0]));
            t1 = ex2(__fmaf_rn(a.y, L2E, noPar ? 0.f : p[0][1]));
            t2 = ex2(__fmaf_rn(a.z, L2E, noPar ? 0.f : p[0][2]));
            t3 = ex2(__fmaf_rn(a.w, L2E, noPar ? 0.f : p[0][3]));
        } else {
            t0 = ex2(__fmaf_rn(a.x, L2E, p[pi][0]));
            t1 = ex2(__fmaf_rn(a.y, L2E, p[pi][1]));
            t2 = ex2(__fmaf_rn(a.z, L2E, p[pi][2]));
            t3 = ex2(__fmaf_rn(a.w, L2E, p[pi][3]));
        }
        z0 += t0; z1 += t1; z2 += t2; z3 += t3;
    }
    float zsum = (z0 + z1) + (z2 + z3);
    #pragma unroll
    for (int off = 16; off; off >>= 1)
        zsum += __shfl_xor_sync(0xffffffffu, zsum, off);

    float lgm;                              // log2(marginal)
    if (label < NC) {                       // warp-uniform rare path (~2.3%)
        const int mmax = (1023 - label) / 24;
        float S = 0.f;
        int m = lane + 1;
        if (m <= mmax) S += ex2(__ldg(fr + label + 24 * m) * L2E);  // L1 hits
        m = lane + 33;
        if (m <= mmax) S += ex2(__ldg(fr + label + 24 * m) * L2E);
        #pragma unroll
        for (int off = 16; off; off >>= 1)
            S += __shfl_xor_sync(0xffffffffu, S, off);
        lgm = mval * L2E + lg2(1.f + S);    // log2(E_label * (1+S))
    } else {
        lgm = (mval + pval) * L2E;          // log2(exp(fs[l] + fs[l%24]))
    }
    return (lg2(1.f + zsum) - lgm) * LN2;
}

// Prefetch one row's data into register buffer B (issued ~1 row ahead).
#define LOADR(B, r)                                                          \
    {                                                                        \
        const float* fr_ = fs + (size_t)(r) * NODES;                         \
        const float4* f4_ = reinterpret_cast<const float4*>(fr_);            \
        _Pragma("unroll")                                                    \
        for (int i_ = 0; i_ < 8; ++i_) v##B[i_] = __ldg(f4_ + i_*32 + lane); \
        lab##B = __ldg(labels + (r));                                        \
        mv##B  = __ldg(fr_ + lab##B);                                        \
        pv##B  = __ldg(fr_ + (lab##B % NC));                                 \
    }

__global__ void __launch_bounds__(THREADS, 5) tree_loss(
    const float* __restrict__ fs, const int* __restrict__ labels,
    float* __restrict__ out)
{
    __shared__ float    s_acc[4];
    __shared__ float    s_red[THREADS];
    __shared__ unsigned s_ticket;

    const int tid   = threadIdx.x;
    const int warp  = tid >> 5;
    const int lane  = tid & 31;
    const int gwarp = blockIdx.x * 4 + warp;

    float4 v0[8], v1[8];
    int lab0, lab1;
    float mv0, pv0, mv1, pv1;

    float acc = 0.f;
    int row = gwarp;                        // < NW <= BATCH always
    LOADR(0, row)

    while (row < BATCH) {
        const int n1 = row + NW;
        if (n1 < BATCH) LOADR(1, n1)        // next row in flight during compute
        acc += row_loss(v0, fs + (size_t)row * NODES, lab0, mv0, pv0, lane);
        row = n1;
        if (row >= BATCH) break;

        const int n2 = row + NW;
        if (n2 < BATCH) LOADR(0, n2)
        acc += row_loss(v1, fs + (size_t)row * NODES, lab1, mv1, pv1, lane);
        row = n2;
    }

    // ---- block sum + deterministic fused final reduction ----
    #pragma unroll
    for (int off = 16; off; off >>= 1)      // acc identical across lanes? no:
        ;                                    // acc is lane-uniform only via shfl'd sums
    if (lane == 0) s_acc[warp] = acc;       // row_loss returns lane-uniform value
    __syncthreads();

    if (tid == 0) {
        g_partial[blockIdx.x] = (s_acc[0] + s_acc[1]) + (s_acc[2] + s_acc[3]);
        __threadfence();
        s_ticket = atomicAdd(&g_count, 1u);
    }
    __syncthreads();

    if (s_ticket == GRID - 1) {             // last block: fixed-order final sum
        float s = 0.f;
        #pragma unroll 2
        for (int k = tid; k < GRID; k += THREADS) s += g_partial[k];
        s_red[tid] = s;
        __syncthreads();
        #pragma unroll
        for (int off = THREADS / 2; off; off >>= 1) {
            if (tid < off) s_red[tid] += s_red[tid + off];
            __syncthreads();
        }
        if (tid == 0) {
            out[0] = s_red[0] * (1.0f / (float)BATCH);
            g_count = 0;                    // reset for next graph replay
        }
    }
}

extern "C" void kernel_launch(void* const* d_in, const int* in_sizes, int n_in,
                              void* d_out, int out_size)
{
    const float* fs     = (const float*)d_in[0];
    const int*   labels = (const int*)d_in[1];
    // d_in[2] = stateSpace: compile-time-known structure, unused.
    tree_loss<<<GRID, THREADS>>>(fs, labels, (float*)d_out);
}